// round 14
// baseline (speedup 1.0000x reference)
#include <cuda_runtime.h>

// Grid: 128^3 cells, cell = (bin+64), idx = x + 128*y + 16384*z
// Each cell: float4 {sum_x, sum_y, sum_z, count}
#define D    128
#define D3   (128*128*128)
#define OFF  64
#define NMAX 200704
#define NBLK 148

__device__ float4 g_gridA[D3];     // scatter ping
__device__ float4 g_gridB[D3];     // scatter pong
__device__ float4 g_grid1[D3];     // conv output / gather source
__device__ float  g_Xbuf[2][NMAX * 3];
__device__ int    g_actA[16 * 128];   // activity flag per (ytile=y>>3, z)
__device__ int    g_actB[16 * 128];
__device__ int    g_tileCtr[8];       // per-step conv tile counters
__device__ unsigned g_maxd2_bits;
__device__ int g_done;
__device__ int g_bar_count;
__device__ volatile int g_bar_gen;

// ---------------------------------------------------------------- helpers
__device__ __forceinline__ int bin_of(float v) {
    // match jnp: (X / 0.1f).astype(int32) == IEEE RN divide, trunc toward zero
    int b = (int)__fdiv_rn(v, 0.1f);
    b += OFF;
    return min(max(b, 0), D - 1);
}

__device__ __forceinline__ void fma4(float4& a, float w, const float4 v) {
    a.x += w * v.x; a.y += w * v.y; a.z += w * v.z; a.w += w * v.w;
}

__device__ __forceinline__ void red4(float4* p, float x, float y, float z, float w) {
    asm volatile("red.global.add.v4.f32 [%0], {%1, %2, %3, %4};"
                 :: "l"(p), "f"(x), "f"(y), "f"(z), "f"(w) : "memory");
}

// software grid barrier: generation counter, all NBLK blocks co-resident
__device__ __forceinline__ void grid_bar() {
    __syncthreads();
    if (threadIdx.x == 0) {
        int gen = g_bar_gen;
        __threadfence();
        if (atomicAdd(&g_bar_count, 1) == NBLK - 1) {
            g_bar_count = 0;
            __threadfence();
            g_bar_gen = gen + 1;
        } else {
            while (g_bar_gen == gen) __nanosleep(64);
        }
        __threadfence();
    }
    __syncthreads();
}

__device__ __forceinline__ void load_slice(const float4* __restrict__ src,
                                           int zc, int x, int r, int y0,
                                           float4& a, float4& b) {
    int zoff = (min(max(zc, 0), D - 1)) << 14;
    int ya = min(max(y0 + r - 2, 0), D - 1);
    a = src[x + (ya << 7) + zoff];
    if (r < 4) {
        int yb = min(max(y0 + r + 6, 0), D - 1);
        b = src[x + (yb << 7) + zoff];
    }
}

// ---------------------------------------------------------------- persistent mega-kernel
// 148 blocks x 1024 threads, 1 block/SM (48KB smem), all phases in one launch:
// scatter0 -> [conv -> gs] x 5, separated by software grid barriers.
__global__ __launch_bounds__(1024) void mega_kernel(const float* __restrict__ Xin,
                                                    float* __restrict__ Out, int n) {
    __shared__ float4 raw[12][D];
    __shared__ float4 xf[12][D];
    __shared__ int s_tile;

    const int tid = threadIdx.x;
    const int x = tid & 127;
    const int lane = tid & 31;
    const int r = tid >> 7;              // 0..7
    const int xm2 = max(x - 2, 0), xm1 = max(x - 1, 0);
    const int xp1 = min(x + 1, D - 1), xp2 = min(x + 2, D - 1);
    const float W0 = 1.f, W1 = 2.f, W2 = 3.f, W3 = 2.f, W4 = 1.f;

    // ---------------- phase: initial scatter ----------------
    for (int i = blockIdx.x * blockDim.x + tid; i < n; i += NBLK * 1024) {
        float px = Xin[3 * i + 0];
        float py = Xin[3 * i + 1];
        float pz = Xin[3 * i + 2];
        int yb = bin_of(py), zb = bin_of(pz);
        int cell = bin_of(px) + (yb << 7) + (zb << 14);
        g_actA[((yb >> 3) << 7) + zb] = 1;
        red4(&g_gridA[cell], px, py, pz, 1.0f);
    }
    grid_bar();

    for (int s = 0; s < 5; s++) {
        int gsel = s & 1;
        // ---------------- phase: conv ----------------
        if (blockIdx.x == 0 && tid == 0) {
            if (s == 0) g_done = 0;
            else if (__uint_as_float(g_maxd2_bits) <= 1e-6f) g_done = 1;
            g_maxd2_bits = 0u;
        }
        {
            const float4* __restrict__ src = gsel ? g_gridB : g_gridA;
            const int* __restrict__ act = gsel ? g_actB : g_actA;
            while (true) {
                if (tid == 0) s_tile = atomicAdd(&g_tileCtr[s], 1);
                __syncthreads();
                int tile = s_tile;
                __syncthreads();
                if (tile >= 256) break;

                int yt = tile & 15;
                int z0 = (tile >> 4) << 3;
                int y0 = yt << 3;

                int f = (lane < 8) ? act[(yt << 7) + z0 + lane] : 0;
                unsigned need = __ballot_sync(0xffffffffu, f != 0) & 0xffu;
                if (!need) continue;
                int zlo = z0 + __ffs(need) - 1;
                int zhi = z0 + 31 - __clz(need);
                int nslices = zhi - zlo + 5;

                float4 r0, r1, r2, r3, r4;
                r0 = r1 = r2 = r3 = r4 = make_float4(0.f, 0.f, 0.f, 0.f);
                float4 pa, pb;
                load_slice(src, zlo - 2, x, r, y0, pa, pb);

#pragma unroll 1
                for (int zi = 0; zi < nslices; zi++) {
                    int zc = zlo - 2 + zi;
                    raw[r][x] = pa;
                    if (r < 4) raw[r + 8][x] = pb;
                    __syncthreads();

                    if (zi < nslices - 1) load_slice(src, zc + 1, x, r, y0, pa, pb);

                    {
                        float4 a = make_float4(0.f, 0.f, 0.f, 0.f);
                        fma4(a, W0, raw[r][xm2]); fma4(a, W1, raw[r][xm1]);
                        fma4(a, W2, raw[r][x]);   fma4(a, W3, raw[r][xp1]);
                        fma4(a, W4, raw[r][xp2]);
                        xf[r][x] = a;
                        if (r < 4) {
                            float4 b = make_float4(0.f, 0.f, 0.f, 0.f);
                            fma4(b, W0, raw[r + 8][xm2]); fma4(b, W1, raw[r + 8][xm1]);
                            fma4(b, W2, raw[r + 8][x]);   fma4(b, W3, raw[r + 8][xp1]);
                            fma4(b, W4, raw[r + 8][xp2]);
                            xf[r + 8][x] = b;
                        }
                    }
                    __syncthreads();

                    float4 a = make_float4(0.f, 0.f, 0.f, 0.f);
                    fma4(a, W0, xf[r + 0][x]);
                    fma4(a, W1, xf[r + 1][x]);
                    fma4(a, W2, xf[r + 2][x]);
                    fma4(a, W3, xf[r + 3][x]);
                    fma4(a, W4, xf[r + 4][x]);

                    r0 = r1; r1 = r2; r2 = r3; r3 = r4; r4 = a;

                    if (zi >= 4) {
                        int zo = zc - 2;
                        float4 o;
                        o.x = r0.x + 2.f * r1.x + 3.f * r2.x + 2.f * r3.x + r4.x;
                        o.y = r0.y + 2.f * r1.y + 3.f * r2.y + 2.f * r3.y + r4.y;
                        o.z = r0.z + 2.f * r1.z + 3.f * r2.z + 2.f * r3.z + r4.z;
                        o.w = r0.w + 2.f * r1.w + 3.f * r2.w + 2.f * r3.w + r4.w;
                        g_grid1[x + ((y0 + r) << 7) + (zo << 14)] = o;
                    }
                }
            }
        }
        grid_bar();

        // ---------------- phase: gather + scatter(next) ----------------
        {
            const float* X = (s == 0) ? Xin : g_Xbuf[(s - 1) & 1];
            float* Y = (s == 4) ? Out : g_Xbuf[s & 1];
            float4* gOld = gsel ? g_gridB : g_gridA;
            float4* gNew = gsel ? g_gridA : g_gridB;
            int* actOld = gsel ? g_actB : g_actA;
            int* actNew = gsel ? g_actA : g_actB;
            int doScatter = (s < 4);

            if (blockIdx.x == 0 && tid == 0)
                g_tileCtr[s] = 0;                  // restore for graph replay

            int done = g_done;
            float d2 = 0.f;
            for (int i = blockIdx.x * blockDim.x + tid; i < n; i += NBLK * 1024) {
                float px = X[3 * i + 0];
                float py = X[3 * i + 1];
                float pz = X[3 * i + 2];
                int yb = bin_of(py), zb = bin_of(pz);
                int cell = bin_of(px) + (yb << 7) + (zb << 14);
                float4 t = g_grid1[cell];
                gOld[cell] = make_float4(0.f, 0.f, 0.f, 0.f);
                actOld[((yb >> 3) << 7) + zb] = 0;
                float nx = __fdiv_rn(t.x, t.w);
                float ny = __fdiv_rn(t.y, t.w);
                float nz = __fdiv_rn(t.z, t.w);
                if (done) { nx = px; ny = py; nz = pz; }
                Y[3 * i + 0] = nx;
                Y[3 * i + 1] = ny;
                Y[3 * i + 2] = nz;
                float dx = nx - px, dy = ny - py, dz = nz - pz;
                d2 = fmaxf(d2, dx * dx + dy * dy + dz * dz);
                if (doScatter) {
                    int nyb = bin_of(ny), nzb = bin_of(nz);
                    int ncell = bin_of(nx) + (nyb << 7) + (nzb << 14);
                    actNew[((nyb >> 3) << 7) + nzb] = 1;
                    red4(&gNew[ncell], nx, ny, nz, 1.0f);
                }
            }
#pragma unroll
            for (int o = 16; o > 0; o >>= 1)
                d2 = fmaxf(d2, __shfl_xor_sync(0xFFFFFFFFu, d2, o));
            if (lane == 0 && d2 > 0.f)
                atomicMax(&g_maxd2_bits, __float_as_uint(d2));
        }
        if (s < 4) grid_bar();
    }
}

// ---------------------------------------------------------------- launch
extern "C" void kernel_launch(void* const* d_in, const int* in_sizes, int n_in,
                              void* d_out, int out_size) {
    const float* Xin = (const float*)d_in[0];
    float* Out = (float*)d_out;
    int n = in_sizes[0] / 3;
    mega_kernel<<<NBLK, 1024>>>(Xin, Out, n);
}

// round 15
// speedup vs baseline: 1.2964x; 1.2964x over previous
#include <cuda_runtime.h>

// Grid: 128^3 cells, cell = (bin+64), idx = x + 128*y + 16384*z
// Each cell: float4 {sum_x, sum_y, sum_z, count}
#define D    128
#define D3   (128*128*128)
#define OFF  64
#define NMAX 200704

__device__ float4 g_gridA[D3];     // scatter ping
__device__ float4 g_gridB[D3];     // scatter pong
__device__ float4 g_grid1[D3];     // yz-smoothed field / gather source
__device__ float  g_Xbuf[2][NMAX * 3];
__device__ int    g_actA[16 * 128];   // activity flag per (ytile=y>>3, z)
__device__ int    g_actB[16 * 128];
__device__ unsigned g_maxd2_bits;
__device__ int g_done;

// ---------------------------------------------------------------- helpers
__device__ __forceinline__ int bin_of(float v) {
    // match jnp: (X / 0.1f).astype(int32) == IEEE RN divide, trunc toward zero
    int b = (int)__fdiv_rn(v, 0.1f);
    b += OFF;
    return min(max(b, 0), D - 1);
}

__device__ __forceinline__ void red4(float4* p, float x, float y, float z, float w) {
    asm volatile("red.global.add.v4.f32 [%0], {%1, %2, %3, %4};"
                 :: "l"(p), "f"(x), "f"(y), "f"(z), "f"(w) : "memory");
}

// (a+e) + 2(b+d) + 3c, componentwise
__device__ __forceinline__ float4 w5(float4 a, float4 b, float4 c, float4 d, float4 e) {
    float4 o;
    o.x = (a.x + e.x) + 2.f * (b.x + d.x) + 3.f * c.x;
    o.y = (a.y + e.y) + 2.f * (b.y + d.y) + 3.f * c.y;
    o.z = (a.z + e.z) + 2.f * (b.z + d.z) + 3.f * c.z;
    o.w = (a.w + e.w) + 2.f * (b.w + d.w) + 3.f * c.w;
    return o;
}

// ---------------------------------------------------------------- initial scatter (step 0 only)
__global__ __launch_bounds__(1024) void scatter0_kernel(const float* __restrict__ X, int n) {
    int i = blockIdx.x * blockDim.x + threadIdx.x;
    if (i >= n) return;
    float x = X[3 * i + 0];
    float y = X[3 * i + 1];
    float z = X[3 * i + 2];
    int yb = bin_of(y), zb = bin_of(z);
    int cell = bin_of(x) + (yb << 7) + (zb << 14);
    g_actA[((yb >> 3) << 7) + zb] = 1;
    red4(&g_gridA[cell], x, y, z, 1.0f);
}

// ---------------------------------------------------------------- y+z separable conv (NO smem, NO syncs)
// weights [1,2,3,2,1] in y and z; the x-filter is applied at gather time.
// Block: full x-line (128) x 8 output y-rows; tile = (ytile, zseg of 8).
// Each thread loads its own 5 y-neighbor rows per slice (L1 serves the 5x
// reuse across r-threads), accumulates a 5-deep z register ring (rotated by
// 5x loop unroll), writes one output row. Zero cross-thread coupling.

__device__ __forceinline__ float4 ysum(const float4* __restrict__ src,
                                       int xo, const int* yo, int zc) {
    const float4* p = src + xo + ((min(max(zc, 0), D - 1)) << 14);
    return w5(p[yo[0]], p[yo[1]], p[yo[2]], p[yo[3]], p[yo[4]]);
}

__global__ __launch_bounds__(1024) void convyz_kernel(int sel, int first) {
    if (blockIdx.x == 0 && threadIdx.x == 0) {
        // fold convergence check: uses previous step's max displacement^2
        if (first) g_done = 0;
        else if (__uint_as_float(g_maxd2_bits) <= 1e-6f) g_done = 1;
        g_maxd2_bits = 0u;
    }

    const float4* __restrict__ src = sel ? g_gridB : g_gridA;
    const int* __restrict__ act = sel ? g_actB : g_actA;

    int x = threadIdx.x & 127;
    int lane = threadIdx.x & 31;
    int r = threadIdx.x >> 7;            // 0..7
    int yt = blockIdx.x & 15;            // 16 y-tiles of 8 rows
    int z0 = (blockIdx.x >> 4) << 3;     // 16 z-segments of 8 slices
    int y0 = yt << 3;

    // per-warp activity ballot (identical in every warp)
    int f = (lane < 8) ? act[(yt << 7) + z0 + lane] : 0;
    unsigned need = __ballot_sync(0xffffffffu, f != 0) & 0xffu;
    if (!need) return;
    int zlo = z0 + __ffs(need) - 1;
    int zhi = z0 + 31 - __clz(need);
    int nsl = zhi - zlo + 5;             // raw slices zlo-2 .. zhi+2

    int yo[5];
#pragma unroll
    for (int j = 0; j < 5; j++)
        yo[j] = (min(max(y0 + r - 2 + j, 0), D - 1)) << 7;

    float4* __restrict__ outp = g_grid1 + x + ((y0 + r) << 7);

    float4 q0, q1, q2, q3, q4;           // z ring of y-smoothed slices
    q0 = q1 = q2 = q3 = q4 = make_float4(0.f, 0.f, 0.f, 0.f);

    int zi = 0;
    while (true) {
        q0 = ysum(src, x, yo, zlo - 2 + zi);
        if (zi >= 4) outp[(zlo - 4 + zi) << 14] = w5(q1, q2, q3, q4, q0);
        if (++zi >= nsl) break;
        q1 = ysum(src, x, yo, zlo - 2 + zi);
        if (zi >= 4) outp[(zlo - 4 + zi) << 14] = w5(q2, q3, q4, q0, q1);
        if (++zi >= nsl) break;
        q2 = ysum(src, x, yo, zlo - 2 + zi);
        if (zi >= 4) outp[(zlo - 4 + zi) << 14] = w5(q3, q4, q0, q1, q2);
        if (++zi >= nsl) break;
        q3 = ysum(src, x, yo, zlo - 2 + zi);
        if (zi >= 4) outp[(zlo - 4 + zi) << 14] = w5(q4, q0, q1, q2, q3);
        if (++zi >= nsl) break;
        q4 = ysum(src, x, yo, zlo - 2 + zi);
        if (zi >= 4) outp[(zlo - 4 + zi) << 14] = w5(q0, q1, q2, q3, q4);
        if (++zi >= nsl) break;
    }
}

// ---------------------------------------------------------------- fused gather + scatter(next)
// Gather now applies the x-filter: 5 taps around the point's cell — all in
// the same / adjacent 128B line (L2-hot). 1 point per thread.
__global__ __launch_bounds__(1024) void fused_gs_kernel(
        const float* __restrict__ Xext, int srcSel,
        float* __restrict__ Oext, int dstSel,
        int gsel, int doScatter, int n) {
    __shared__ float s_max[32];
    const float* X = (srcSel < 0) ? Xext : g_Xbuf[srcSel];
    float* Y = (dstSel < 0) ? Oext : g_Xbuf[dstSel];
    float4* gOld = gsel ? g_gridB : g_gridA;   // consumed this step -> zero
    float4* gNew = gsel ? g_gridA : g_gridB;   // next step's scatter target
    int* actOld = gsel ? g_actB : g_actA;
    int* actNew = gsel ? g_actA : g_actB;

    int i = blockIdx.x * blockDim.x + threadIdx.x;
    float d2 = 0.f;
    if (i < n) {
        float x = X[3 * i + 0];
        float y = X[3 * i + 1];
        float z = X[3 * i + 2];
        int xb = bin_of(x), yb = bin_of(y), zb = bin_of(z);
        int rowbase = (yb << 7) + (zb << 14);
        int cell = xb + rowbase;
        // x-filter from the yz-smoothed field (same cache line mostly)
        const float4* __restrict__ g = g_grid1 + rowbase;
        float4 t = w5(g[max(xb - 2, 0)], g[max(xb - 1, 0)], g[xb],
                      g[min(xb + 1, D - 1)], g[min(xb + 2, D - 1)]);
        // undo this step's scatter: keeps grids & flags all-zero at boundaries
        gOld[cell] = make_float4(0.f, 0.f, 0.f, 0.f);
        actOld[((yb >> 3) << 7) + zb] = 0;
        float nx = __fdiv_rn(t.x, t.w);
        float ny = __fdiv_rn(t.y, t.w);
        float nz = __fdiv_rn(t.z, t.w);
        if (g_done) { nx = x; ny = y; nz = z; }
        Y[3 * i + 0] = nx;
        Y[3 * i + 1] = ny;
        Y[3 * i + 2] = nz;
        float dx = nx - x, dy = ny - y, dz = nz - z;
        d2 = dx * dx + dy * dy + dz * dz;
        if (doScatter) {
            int nyb = bin_of(ny), nzb = bin_of(nz);
            int ncell = bin_of(nx) + (nyb << 7) + (nzb << 14);
            actNew[((nyb >> 3) << 7) + nzb] = 1;
            red4(&gNew[ncell], nx, ny, nz, 1.0f);
        }
    }
#pragma unroll
    for (int o = 16; o > 0; o >>= 1)
        d2 = fmaxf(d2, __shfl_xor_sync(0xFFFFFFFFu, d2, o));
    int wid = threadIdx.x >> 5;
    if ((threadIdx.x & 31) == 0) s_max[wid] = d2;
    __syncthreads();
    if (threadIdx.x < 32) {
        float v = s_max[threadIdx.x];
#pragma unroll
        for (int o = 16; o > 0; o >>= 1)
            v = fmaxf(v, __shfl_xor_sync(0xFFFFFFFFu, v, o));
        if (threadIdx.x == 0)
            atomicMax(&g_maxd2_bits, __float_as_uint(v));
    }
}

// ---------------------------------------------------------------- launch
extern "C" void kernel_launch(void* const* d_in, const int* in_sizes, int n_in,
                              void* d_out, int out_size) {
    const float* Xin = (const float*)d_in[0];
    float* Out = (float*)d_out;
    int n = in_sizes[0] / 3;

    int pblocks = (n + 1023) / 1024;
    int srcSel[5] = {-1, 0, 1, 0, 1};
    int dstSel[5] = { 0, 1, 0, 1, -1};

    scatter0_kernel<<<pblocks, 1024>>>(Xin, n);
    for (int s = 0; s < 5; s++) {
        int gsel = s & 1;
        convyz_kernel<<<256, 1024>>>(gsel, s == 0);
        fused_gs_kernel<<<pblocks, 1024>>>(Xin, srcSel[s], Out, dstSel[s],
                                           gsel, s < 4, n);
    }
}